// round 14
// baseline (speedup 1.0000x reference)
#include <cuda_runtime.h>
#include <cuda_bf16.h>
#include <math.h>
#include <cstdint>

// Problem constants
#define BB 256
#define TT 16
#define SS 20
#define DD 256
#define NN (BB*TT)          // 4096
#define TD (3*DD)           // 768
#define NC 1536             // 2*TD columns of precompute GEMM
#define NITEMS 100000

// ---------------- device scratch ----------------
__device__ float g_G[(size_t)SS * NN * NC];   // [s][n][1536]  (503 MB)
__device__ float g_h[NN * DD];                // hidden state (f32)
__device__ float g_m[NN];                     // soft readout multiplier
__device__ float g_gh[NN * TD];               // per-step h @ W_hh^T

// packed bf16 (two consecutive k per u32; low 16 = even k)
__device__ uint32_t g_iT_hi[(size_t)NITEMS * 128];
__device__ uint32_t g_iT_lo[(size_t)NITEMS * 128];
__device__ uint32_t g_Wih_hi[NC * 128];
__device__ uint32_t g_Wih_lo[NC * 128];
__device__ uint32_t g_Whh_hi[TD * 128];
__device__ uint32_t g_Whh_lo[TD * 128];
__device__ uint32_t g_h_hi[NN * 128];
__device__ uint32_t g_h_lo[NN * 128];

// ---------------- helpers ----------------
__device__ __forceinline__ uint32_t smem_u32(const void* p) {
    uint32_t a;
    asm("{ .reg .u64 t; cvta.to.shared.u64 t, %1; cvt.u32.u64 %0, t; }"
        : "=r"(a) : "l"(p));
    return a;
}
__device__ __forceinline__ void cp16(uint32_t dst, const void* src) {
    asm volatile("cp.async.cg.shared.global [%0], [%1], 16;"
                 :: "r"(dst), "l"(src) : "memory");
}
__device__ __forceinline__ void cp_commit() {
    asm volatile("cp.async.commit_group;" ::: "memory");
}
template<int N>
__device__ __forceinline__ void cp_wait() {
    asm volatile("cp.async.wait_group %0;" :: "n"(N) : "memory");
}
__device__ __forceinline__ void ldmx4(uint32_t& r0, uint32_t& r1,
                                      uint32_t& r2, uint32_t& r3, uint32_t addr) {
    asm volatile("ldmatrix.sync.aligned.m8n8.x4.shared.b16 {%0,%1,%2,%3}, [%4];"
                 : "=r"(r0), "=r"(r1), "=r"(r2), "=r"(r3) : "r"(addr));
}

// split two consecutive floats into bf16x2 hi + bf16x2 lo packs
__device__ __forceinline__ void split2(float2 v, uint32_t& hi, uint32_t& lo) {
    __nv_bfloat16 hx = __float2bfloat16_rn(v.x);
    __nv_bfloat16 hy = __float2bfloat16_rn(v.y);
    float rx = v.x - __bfloat162float(hx);
    float ry = v.y - __bfloat162float(hy);
    __nv_bfloat162 h2 = __halves2bfloat162(hx, hy);
    __nv_bfloat162 l2 = __halves2bfloat162(__float2bfloat16_rn(rx),
                                           __float2bfloat16_rn(ry));
    hi = *reinterpret_cast<uint32_t*>(&h2);
    lo = *reinterpret_cast<uint32_t*>(&l2);
}

__device__ __forceinline__ void mma_bf16(float c[4],
                                         uint32_t a0, uint32_t a1, uint32_t a2, uint32_t a3,
                                         uint32_t b0, uint32_t b1) {
    asm volatile(
        "mma.sync.aligned.m16n8k16.row.col.f32.bf16.bf16.f32 "
        "{%0,%1,%2,%3}, {%4,%5,%6,%7}, {%8,%9}, {%0,%1,%2,%3};"
        : "+f"(c[0]), "+f"(c[1]), "+f"(c[2]), "+f"(c[3])
        : "r"(a0), "r"(a1), "r"(a2), "r"(a3), "r"(b0), "r"(b1));
}

// ---------------- conversion prep kernels ----------------
__global__ void conv_item(const float* __restrict__ item_table) {
    size_t p = (size_t)blockIdx.x * blockDim.x + threadIdx.x;
    if (p >= (size_t)NITEMS * 128) return;
    float2 v = *(const float2*)(item_table + 2 * p);
    split2(v, g_iT_hi[p], g_iT_lo[p]);
}
__global__ void conv_wih(const float* __restrict__ W_ih) {
    int j = blockIdx.x;       // 0..1535
    int p = threadIdx.x;      // 0..127
    int jj = (j >= TD) ? (j - TD) : j;
    const float* src = W_ih + (size_t)jj * (2 * DD) + (j >= TD ? DD : 0) + 2 * p;
    split2(make_float2(src[0], src[1]), g_Wih_hi[j * 128 + p], g_Wih_lo[j * 128 + p]);
}
__global__ void conv_whh(const float* __restrict__ W_hh) {
    int j = blockIdx.x;       // 0..767
    int p = threadIdx.x;      // 0..127
    const float* src = W_hh + (size_t)j * DD + 2 * p;
    split2(make_float2(src[0], src[1]), g_Whh_hi[j * 128 + p], g_Whh_lo[j * 128 + p]);
}

// ---------------- GEMM ----------------
#define PSTR 20                                // u32 stride per smem row

// ===== pre-split bf16 (3-term) GEMM, tile M=64 x N=256, ldmatrix loads =====
// 8 warps = 2 warpM (32 rows each) x 4 warpN (64 cols each).
// K=256 in 8 chunks of 32, cp.async double buffered.
// AMODE 1: A row r -> item row item_idxs[n*20+s], r = s*4096+n. Else row r.
template<int AMODE>
__global__ __launch_bounds__(256, 2)
void gemm_tc(const uint32_t* __restrict__ Ahi, const uint32_t* __restrict__ Alo,
             const uint32_t* __restrict__ Bhi, const uint32_t* __restrict__ Blo,
             float* __restrict__ C, int Ncols,
             const int* __restrict__ item_idxs) {
    constexpr int ROWSA   = 64;
    constexpr int COLSB   = 256;
    constexpr int A_T_U32 = ROWSA * PSTR;      // 1280
    constexpr int B_T_U32 = COLSB * PSTR;      // 5120
    constexpr int STAGE_B = (2 * A_T_U32 + 2 * B_T_U32) * 4;  // 51200

    extern __shared__ char smem[];
    const uint32_t smem_base = smem_u32(smem);
    const int tid  = threadIdx.x;
    const int wid  = tid >> 5;
    const int lane = tid & 31;
    const int bx = blockIdx.x, by = blockIdx.y;

    uint32_t* offA = (uint32_t*)(smem);          // 64 entries
    uint32_t* offB = (uint32_t*)(smem + 256);    // 256 entries

    if (tid < ROWSA) {
        int r = by * ROWSA + tid;
        uint32_t off;
        if (AMODE == 1) {
            int s = r >> 12, n = r & 4095;
            off = (uint32_t)item_idxs[n * SS + s] * 128u;
        } else {
            off = (uint32_t)r * 128u;
        }
        offA[tid] = off;
    }
    {
        int j = bx * COLSB + tid;
        offB[tid] = (uint32_t)j * 128u;
    }
    __syncthreads();

    // ---- async tile copy: 16B units, order [Ahi][Alo][Bhi][Blo] ----
    const uint32_t stage0 = smem_base + 1536;
    auto prefetch = [&](int kc, int buf) {
        const uint32_t sb = stage0 + (uint32_t)buf * STAGE_B;
        const uint32_t ko = (uint32_t)kc * 16;   // u32 per K=32 chunk
        // A units: 2*64*4 = 512 ; B units: 2*256*4 = 2048 ; total 2560
#pragma unroll
        for (int it = 0; it < 10; it++) {
            int u = tid + it * 256;
            const uint32_t* src;
            uint32_t dst;
            if (u < 512) {
                int t = u >> 8;                  // 0=hi 1=lo
                int v = u & 255;
                int row = v >> 2, q = v & 3;
                src = (t ? Alo : Ahi) + offA[row] + ko + q * 4;
                dst = sb + (uint32_t)(t * A_T_U32 + row * PSTR + q * 4) * 4u;
            } else {
                int w = u - 512;
                int t = w >> 10;
                int v = w & 1023;
                int row = v >> 2, q = v & 3;
                src = (t ? Blo : Bhi) + offB[row] + ko + q * 4;
                dst = sb + (uint32_t)(2 * A_T_U32 + t * B_T_U32 + row * PSTR + q * 4) * 4u;
            }
            cp16(dst, src);
        }
    };

    const int warpM = wid & 1;
    const int warpN = wid >> 1;
    const int mb = warpM * 32;
    const int nb = warpN * 64;
    const int sel = lane >> 3;
    const int rl  = lane & 7;

    // per-lane ldmatrix row byte-offsets (within a tile)
    int aRowOff[2], bRowOff[4];
#pragma unroll
    for (int mt = 0; mt < 2; mt++)
        aRowOff[mt] = (mb + mt * 16 + (sel & 1) * 8 + rl) * (PSTR * 4) + (sel >> 1) * 16;
#pragma unroll
    for (int p = 0; p < 4; p++)
        bRowOff[p] = (nb + p * 16 + (sel >> 1) * 8 + rl) * (PSTR * 4) + (sel & 1) * 16;

    float c[2][8][4];
#pragma unroll
    for (int mt = 0; mt < 2; mt++)
#pragma unroll
        for (int nt = 0; nt < 8; nt++)
#pragma unroll
            for (int e = 0; e < 4; e++) c[mt][nt][e] = 0.0f;

    prefetch(0, 0);
    cp_commit();

    for (int kc = 0; kc < 8; kc++) {
        if (kc < 7) {
            prefetch(kc + 1, (kc + 1) & 1);
            cp_commit();
            cp_wait<1>();
        } else {
            cp_wait<0>();
        }
        __syncthreads();

        const uint32_t sb   = stage0 + (uint32_t)(kc & 1) * STAGE_B;
        const uint32_t AhiB = sb;
        const uint32_t AloB = sb + A_T_U32 * 4;
        const uint32_t BhiB = sb + 2 * A_T_U32 * 4;
        const uint32_t BloB = BhiB + B_T_U32 * 4;

#pragma unroll
        for (int ks = 0; ks < 2; ks++) {
            const int kofs = ks * 32;
            // A fragments for both m-tiles (held across the p loop)
            uint32_t ah[2][4], al[2][4];
#pragma unroll
            for (int mt = 0; mt < 2; mt++) {
                ldmx4(ah[mt][0], ah[mt][1], ah[mt][2], ah[mt][3], AhiB + aRowOff[mt] + kofs);
                ldmx4(al[mt][0], al[mt][1], al[mt][2], al[mt][3], AloB + aRowOff[mt] + kofs);
            }
            // stream B in 4 pairs (8 live frag regs)
#pragma unroll
            for (int p = 0; p < 4; p++) {
                uint32_t bh0, bh1, bh2, bh3, bl0, bl1, bl2, bl3;
                ldmx4(bh0, bh1, bh2, bh3, BhiB + bRowOff[p] + kofs);
                ldmx4(bl0, bl1, bl2, bl3, BloB + bRowOff[p] + kofs);
#pragma unroll
                for (int mt = 0; mt < 2; mt++) {
                    mma_bf16(c[mt][2*p],   al[mt][0], al[mt][1], al[mt][2], al[mt][3], bh0, bh1);
                    mma_bf16(c[mt][2*p],   ah[mt][0], ah[mt][1], ah[mt][2], ah[mt][3], bl0, bl1);
                    mma_bf16(c[mt][2*p],   ah[mt][0], ah[mt][1], ah[mt][2], ah[mt][3], bh0, bh1);
                    mma_bf16(c[mt][2*p+1], al[mt][0], al[mt][1], al[mt][2], al[mt][3], bh2, bh3);
                    mma_bf16(c[mt][2*p+1], ah[mt][0], ah[mt][1], ah[mt][2], ah[mt][3], bl2, bl3);
                    mma_bf16(c[mt][2*p+1], ah[mt][0], ah[mt][1], ah[mt][2], ah[mt][3], bh2, bh3);
                }
            }
        }
        __syncthreads();
    }

    // epilogue: c0,c1 -> (row g, cols 2tg,2tg+1), c2,c3 -> (row g+8)
    const int g  = lane >> 2;
    const int tg = lane & 3;
#pragma unroll
    for (int mt = 0; mt < 2; mt++) {
        int row0 = by * ROWSA + mb + mt * 16 + g;
        int row1 = row0 + 8;
        float* c0p = C + (size_t)row0 * Ncols + bx * COLSB + nb;
        float* c1p = C + (size_t)row1 * Ncols + bx * COLSB + nb;
#pragma unroll
        for (int nt = 0; nt < 8; nt++) {
            int col = nt * 8 + tg * 2;
            *(float2*)(c0p + col) = make_float2(c[mt][nt][0], c[mt][nt][1]);
            *(float2*)(c1p + col) = make_float2(c[mt][nt][2], c[mt][nt][3]);
        }
    }
}

// ---------------- init h, m (f32 + packed), 64 threads float4 ----------------
__global__ void init_hm(const int* __restrict__ user_idxs,
                        const float* __restrict__ user_table) {
    int n = blockIdx.x;
    int t = threadIdx.x;    // 0..63
    float4 hv = *(const float4*)(user_table + (size_t)user_idxs[n] * DD + 4 * t);
    *(float4*)(g_h + n * DD + 4 * t) = hv;
    uint32_t hi0, lo0, hi1, lo1;
    split2(make_float2(hv.x, hv.y), hi0, lo0);
    split2(make_float2(hv.z, hv.w), hi1, lo1);
    g_h_hi[n * 128 + 2 * t]     = hi0;
    g_h_lo[n * 128 + 2 * t]     = lo0;
    g_h_hi[n * 128 + 2 * t + 1] = hi1;
    g_h_lo[n * 128 + 2 * t + 1] = lo1;
    if (t == 0) g_m[n] = 1.0f;
}

// ---------------- fused GRU gates + y + state update (64 thr, float4) -------
__device__ __forceinline__ float sigmoidf_(float x) {
    return 1.0f / (1.0f + expf(-x));
}

__global__ __launch_bounds__(64)
void gru_step(const float* __restrict__ b_ih,
              const float* __restrict__ b_hh,
              const float* __restrict__ W_out,
              const float* __restrict__ b_out,
              float* __restrict__ out,
              int s) {
    const int n = blockIdx.x;
    const int t = threadIdx.x;   // 0..63, handles cols 4t..4t+3

    const float* Grow  = g_G + ((size_t)s * NN + n) * NC;
    const float* ghrow = g_gh + (size_t)n * TD;

    float mm = g_m[n];
    float4 hv = *(const float4*)(g_h + n * DD + 4 * t);

    float4 Gr = *(const float4*)(Grow + 4 * t);
    float4 Gz = *(const float4*)(Grow + DD + 4 * t);
    float4 Gn = *(const float4*)(Grow + 2 * DD + 4 * t);
    float4 Mr = *(const float4*)(Grow + TD + 4 * t);
    float4 Mz = *(const float4*)(Grow + TD + DD + 4 * t);
    float4 Mn = *(const float4*)(Grow + TD + 2 * DD + 4 * t);
    float4 Hr = *(const float4*)(ghrow + 4 * t);
    float4 Hz = *(const float4*)(ghrow + DD + 4 * t);
    float4 Hn = *(const float4*)(ghrow + 2 * DD + 4 * t);
    float4 Br = *(const float4*)(b_ih + 4 * t);
    float4 Bz = *(const float4*)(b_ih + DD + 4 * t);
    float4 Bn = *(const float4*)(b_ih + 2 * DD + 4 * t);
    float4 Cr = *(const float4*)(b_hh + 4 * t);
    float4 Cz = *(const float4*)(b_hh + DD + 4 * t);
    float4 Cn = *(const float4*)(b_hh + 2 * DD + 4 * t);
    float4 Wo = *(const float4*)(W_out + 4 * t);

    float hn[4], hvv[4] = {hv.x, hv.y, hv.z, hv.w};
    float gr[4] = {Gr.x,Gr.y,Gr.z,Gr.w}, gz[4] = {Gz.x,Gz.y,Gz.z,Gz.w}, gn[4] = {Gn.x,Gn.y,Gn.z,Gn.w};
    float mr[4] = {Mr.x,Mr.y,Mr.z,Mr.w}, mz[4] = {Mz.x,Mz.y,Mz.z,Mz.w}, mn[4] = {Mn.x,Mn.y,Mn.z,Mn.w};
    float hr[4] = {Hr.x,Hr.y,Hr.z,Hr.w}, hz[4] = {Hz.x,Hz.y,Hz.z,Hz.w}, hnn[4] = {Hn.x,Hn.y,Hn.z,Hn.w};
    float br[4] = {Br.x,Br.y,Br.z,Br.w}, bz[4] = {Bz.x,Bz.y,Bz.z,Bz.w}, bn[4] = {Bn.x,Bn.y,Bn.z,Bn.w};
    float cr[4] = {Cr.x,Cr.y,Cr.z,Cr.w}, cz[4] = {Cz.x,Cz.y,Cz.z,Cz.w}, cn[4] = {Cn.x,Cn.y,Cn.z,Cn.w};
    float wo[4] = {Wo.x,Wo.y,Wo.z,Wo.w};

    float part = 0.0f;
#pragma unroll
    for (int e = 0; e < 4; e++) {
        float gir = gr[e] + mm * mr[e] + br[e];
        float giz = gz[e] + mm * mz[e] + bz[e];
        float gin = gn[e] + mm * mn[e] + bn[e];
        float ghr = hr[e] + cr[e];
        float ghz = hz[e] + cz[e];
        float ghn = hnn[e] + cn[e];
        float r  = sigmoidf_(gir + ghr);
        float z  = sigmoidf_(giz + ghz);
        float nv = tanhf(gin + r * ghn);
        hn[e] = (1.0f - z) * nv + z * hvv[e];
        part += hn[e] * wo[e];
    }

    *(float4*)(g_h + n * DD + 4 * t) = make_float4(hn[0], hn[1], hn[2], hn[3]);
    uint32_t hi0, lo0, hi1, lo1;
    split2(make_float2(hn[0], hn[1]), hi0, lo0);
    split2(make_float2(hn[2], hn[3]), hi1, lo1);
    g_h_hi[n * 128 + 2 * t]     = hi0;
    g_h_lo[n * 128 + 2 * t]     = lo0;
    g_h_hi[n * 128 + 2 * t + 1] = hi1;
    g_h_lo[n * 128 + 2 * t + 1] = lo1;

#pragma unroll
    for (int off = 16; off > 0; off >>= 1)
        part += __shfl_down_sync(0xFFFFFFFFu, part, off);

    __shared__ float warpsum[2];
    if ((t & 31) == 0) warpsum[t >> 5] = part;
    __syncthreads();
    if (t == 0) {
        float y = b_out[0] + warpsum[0] + warpsum[1];
        out[n * SS + s] = y;
        g_m[n] = sigmoidf_(y);
    }
}

// ---------------- launch ----------------
extern "C" void kernel_launch(void* const* d_in, const int* in_sizes, int n_in,
                              void* d_out, int out_size) {
    const int*   item_idxs  = (const int*)  d_in[0];
    const int*   user_idxs  = (const int*)  d_in[1];
    const float* item_table = (const float*)d_in[3];
    const float* user_table = (const float*)d_in[4];
    const float* W_ih       = (const float*)d_in[5];
    const float* W_hh       = (const float*)d_in[6];
    const float* b_ih       = (const float*)d_in[7];
    const float* b_hh       = (const float*)d_in[8];
    const float* W_out      = (const float*)d_in[9];
    const float* b_out      = (const float*)d_in[10];
    float* out = (float*)d_out;

    float *G_p, *gh_p;
    uint32_t *iTh, *iTl, *Wih_h, *Wih_l, *Whh_h, *Whh_l, *hh, *hl;
    cudaGetSymbolAddress((void**)&G_p,  g_G);
    cudaGetSymbolAddress((void**)&gh_p, g_gh);
    cudaGetSymbolAddress((void**)&iTh,  g_iT_hi);
    cudaGetSymbolAddress((void**)&iTl,  g_iT_lo);
    cudaGetSymbolAddress((void**)&Wih_h, g_Wih_hi);
    cudaGetSymbolAddress((void**)&Wih_l, g_Wih_lo);
    cudaGetSymbolAddress((void**)&Whh_h, g_Whh_hi);
    cudaGetSymbolAddress((void**)&Whh_l, g_Whh_lo);
    cudaGetSymbolAddress((void**)&hh,   g_h_hi);
    cudaGetSymbolAddress((void**)&hl,   g_h_lo);

    // smem: 1536 + 2*51200 = 103936 bytes
    const int SMB = 103936;
    cudaFuncSetAttribute(gemm_tc<1>, cudaFuncAttributeMaxDynamicSharedMemorySize, SMB);
    cudaFuncSetAttribute(gemm_tc<0>, cudaFuncAttributeMaxDynamicSharedMemorySize, SMB);

    // one-time conversions
    conv_item<<<(NITEMS * 128 + 255) / 256, 256>>>(item_table);
    conv_wih<<<NC, 128>>>(W_ih);
    conv_whh<<<TD, 128>>>(W_hh);
    init_hm<<<NN, 64>>>(user_idxs, user_table);

    // precompute G = gather(E) @ [W1 | W2]^T   (M=81920, Ncols=1536, K=256)
    {
        dim3 grid(NC / 256, (SS * NN) / 64);    // 6 x 1280
        gemm_tc<1><<<grid, 256, SMB>>>(iTh, iTl, Wih_h, Wih_l,
                                       G_p, NC, item_idxs);
    }

    // 20 sequential GRU steps
    for (int s = 0; s < SS; s++) {
        dim3 grid(TD / 256, NN / 64);           // 3 x 64
        gemm_tc<0><<<grid, 256, SMB>>>(hh, hl, Whh_h, Whh_l,
                                       gh_p, TD, nullptr);
        gru_step<<<NN, 64>>>(b_ih, b_hh, W_out, b_out, out, s);
    }
}

// round 15
// speedup vs baseline: 1.0966x; 1.0966x over previous
#include <cuda_runtime.h>
#include <cuda_bf16.h>
#include <math.h>
#include <cstdint>

// Problem constants
#define BB 256
#define TT 16
#define SS 20
#define DD 256
#define NN (BB*TT)          // 4096
#define TD (3*DD)           // 768
#define NC 1536             // 2*TD columns of precompute GEMM
#define NITEMS 100000

// ---------------- device scratch ----------------
__device__ float g_G[(size_t)SS * NN * NC];   // [s][n][1536]  (503 MB)
__device__ float g_h[NN * DD];                // hidden state (f32)
__device__ float g_m[NN];                     // soft readout multiplier
__device__ float g_gh[NN * TD];               // per-step h @ W_hh^T

// packed bf16 (two consecutive k per u32; low 16 = even k)
__device__ uint32_t g_iT_hi[(size_t)NITEMS * 128];
__device__ uint32_t g_iT_lo[(size_t)NITEMS * 128];
__device__ uint32_t g_Wih_hi[NC * 128];
__device__ uint32_t g_Wih_lo[NC * 128];
__device__ uint32_t g_Whh_hi[TD * 128];
__device__ uint32_t g_Whh_lo[TD * 128];
__device__ uint32_t g_h_hi[NN * 128];
__device__ uint32_t g_h_lo[NN * 128];

// ---------------- helpers ----------------
__device__ __forceinline__ uint32_t smem_u32(const void* p) {
    uint32_t a;
    asm("{ .reg .u64 t; cvta.to.shared.u64 t, %1; cvt.u32.u64 %0, t; }"
        : "=r"(a) : "l"(p));
    return a;
}
__device__ __forceinline__ void cp16(uint32_t dst, const void* src) {
    asm volatile("cp.async.cg.shared.global [%0], [%1], 16;"
                 :: "r"(dst), "l"(src) : "memory");
}
__device__ __forceinline__ void cp_commit() {
    asm volatile("cp.async.commit_group;" ::: "memory");
}
template<int N>
__device__ __forceinline__ void cp_wait() {
    asm volatile("cp.async.wait_group %0;" :: "n"(N) : "memory");
}
__device__ __forceinline__ void ldmx4(uint32_t& r0, uint32_t& r1,
                                      uint32_t& r2, uint32_t& r3, uint32_t addr) {
    asm volatile("ldmatrix.sync.aligned.m8n8.x4.shared.b16 {%0,%1,%2,%3}, [%4];"
                 : "=r"(r0), "=r"(r1), "=r"(r2), "=r"(r3) : "r"(addr));
}

// split two consecutive floats into bf16x2 hi + bf16x2 lo packs
__device__ __forceinline__ void split2(float2 v, uint32_t& hi, uint32_t& lo) {
    __nv_bfloat16 hx = __float2bfloat16_rn(v.x);
    __nv_bfloat16 hy = __float2bfloat16_rn(v.y);
    float rx = v.x - __bfloat162float(hx);
    float ry = v.y - __bfloat162float(hy);
    __nv_bfloat162 h2 = __halves2bfloat162(hx, hy);
    __nv_bfloat162 l2 = __halves2bfloat162(__float2bfloat16_rn(rx),
                                           __float2bfloat16_rn(ry));
    hi = *reinterpret_cast<uint32_t*>(&h2);
    lo = *reinterpret_cast<uint32_t*>(&l2);
}

__device__ __forceinline__ void mma_bf16(float c[4],
                                         uint32_t a0, uint32_t a1, uint32_t a2, uint32_t a3,
                                         uint32_t b0, uint32_t b1) {
    asm volatile(
        "mma.sync.aligned.m16n8k16.row.col.f32.bf16.bf16.f32 "
        "{%0,%1,%2,%3}, {%4,%5,%6,%7}, {%8,%9}, {%0,%1,%2,%3};"
        : "+f"(c[0]), "+f"(c[1]), "+f"(c[2]), "+f"(c[3])
        : "r"(a0), "r"(a1), "r"(a2), "r"(a3), "r"(b0), "r"(b1));
}

// ---------------- conversion prep kernels ----------------
__global__ void conv_item(const float* __restrict__ item_table) {
    size_t p = (size_t)blockIdx.x * blockDim.x + threadIdx.x;
    if (p >= (size_t)NITEMS * 128) return;
    float2 v = *(const float2*)(item_table + 2 * p);
    split2(v, g_iT_hi[p], g_iT_lo[p]);
}
__global__ void conv_wih(const float* __restrict__ W_ih) {
    int j = blockIdx.x;       // 0..1535
    int p = threadIdx.x;      // 0..127
    int jj = (j >= TD) ? (j - TD) : j;
    const float* src = W_ih + (size_t)jj * (2 * DD) + (j >= TD ? DD : 0) + 2 * p;
    split2(make_float2(src[0], src[1]), g_Wih_hi[j * 128 + p], g_Wih_lo[j * 128 + p]);
}
__global__ void conv_whh(const float* __restrict__ W_hh) {
    int j = blockIdx.x;       // 0..767
    int p = threadIdx.x;      // 0..127
    const float* src = W_hh + (size_t)j * DD + 2 * p;
    split2(make_float2(src[0], src[1]), g_Whh_hi[j * 128 + p], g_Whh_lo[j * 128 + p]);
}

// ---------------- GEMM ----------------
#define PSTR 20                                // u32 stride per smem row

// ===== pre-split bf16 (3-term) GEMM with ldmatrix fragment loads =====
// Tile: M = 32*MTN (MTN per-warp 16-row blocks x 2 warpM), N = 128.
// K=256 in 8 chunks of 32, cp.async double buffered.
// AMODE 1: A row r -> item row item_idxs[n*20+s], r = s*4096+n. Else row r.
template<int AMODE, int MTN>
__global__ __launch_bounds__(256)
void gemm_tc(const uint32_t* __restrict__ Ahi, const uint32_t* __restrict__ Alo,
             const uint32_t* __restrict__ Bhi, const uint32_t* __restrict__ Blo,
             float* __restrict__ C, int Ncols,
             const int* __restrict__ item_idxs) {
    constexpr int ROWSA   = 32 * MTN;
    constexpr int A_T_U32 = ROWSA * PSTR;
    constexpr int B_T_U32 = 128 * PSTR;
    constexpr int STAGE_U32 = 2 * A_T_U32 + 2 * B_T_U32;
    constexpr int STAGE_B   = STAGE_U32 * 4;

    extern __shared__ char smem[];
    const uint32_t smem_base = smem_u32(smem);
    const int tid  = threadIdx.x;
    const int wid  = tid >> 5;
    const int lane = tid & 31;
    const int bx = blockIdx.x, by = blockIdx.y;

    uint32_t* offA = (uint32_t*)(smem);          // ROWSA entries
    uint32_t* offB = (uint32_t*)(smem + 512);    // 128 entries

    if (tid < ROWSA) {
        int r = by * ROWSA + tid;
        uint32_t off;
        if (AMODE == 1) {
            int s = r >> 12, n = r & 4095;
            off = (uint32_t)item_idxs[n * SS + s] * 128u;
        } else {
            off = (uint32_t)r * 128u;
        }
        offA[tid] = off;
    } else if (tid >= 128) {
        int j = bx * 128 + (tid - 128);
        offB[tid - 128] = (uint32_t)j * 128u;
    }
    __syncthreads();

    // ---- async tile copy: 16B units, order [Ahi][Alo][Bhi][Blo] ----
    const uint32_t stage0 = smem_base + 1024;
    auto prefetch = [&](int kc, int buf) {
        const uint32_t sb = stage0 + (uint32_t)buf * STAGE_B;
        const uint32_t ko = (uint32_t)kc * 16;   // u32 per K=32 chunk
        constexpr int UA = ROWSA * 4;            // units per A tile
        constexpr int UB = 128 * 4;
        constexpr int TOT = 2 * UA + 2 * UB;
        for (int u = tid; u < TOT; u += 256) {
            const uint32_t* src;
            uint32_t dst;
            if (u < 2 * UA) {
                int t = u / UA;                  // 0=hi 1=lo
                int v = u - t * UA;
                int row = v >> 2, q = v & 3;
                src = (t ? Alo : Ahi) + offA[row] + ko + q * 4;
                dst = sb + (uint32_t)(t * A_T_U32 + row * PSTR + q * 4) * 4u;
            } else {
                int w = u - 2 * UA;
                int t = w / UB;
                int v = w - t * UB;
                int row = v >> 2, q = v & 3;
                src = (t ? Blo : Bhi) + offB[row] + ko + q * 4;
                dst = sb + (uint32_t)(2 * A_T_U32 + t * B_T_U32 + row * PSTR + q * 4) * 4u;
            }
            cp16(dst, src);
        }
    };

    const int warpM = wid & 1;
    const int warpN = wid >> 1;
    const int mb = warpM * (16 * MTN);
    const int nb = warpN * 32;
    const int sel = lane >> 3;
    const int rl  = lane & 7;

    // per-lane ldmatrix row byte-offsets (within a tile)
    int aRowOff[MTN], bRowOff[2];
#pragma unroll
    for (int mt = 0; mt < MTN; mt++)
        aRowOff[mt] = (mb + mt * 16 + (sel & 1) * 8 + rl) * (PSTR * 4) + (sel >> 1) * 16;
#pragma unroll
    for (int p = 0; p < 2; p++)
        bRowOff[p] = (nb + p * 16 + (sel >> 1) * 8 + rl) * (PSTR * 4) + (sel & 1) * 16;

    float c[MTN][4][4];
#pragma unroll
    for (int mt = 0; mt < MTN; mt++)
#pragma unroll
        for (int nt = 0; nt < 4; nt++)
#pragma unroll
            for (int e = 0; e < 4; e++) c[mt][nt][e] = 0.0f;

    prefetch(0, 0);
    cp_commit();

    for (int kc = 0; kc < 8; kc++) {
        if (kc < 7) {
            prefetch(kc + 1, (kc + 1) & 1);
            cp_commit();
            cp_wait<1>();
        } else {
            cp_wait<0>();
        }
        __syncthreads();

        const uint32_t sb   = stage0 + (uint32_t)(kc & 1) * STAGE_B;
        const uint32_t AhiB = sb;
        const uint32_t AloB = sb + A_T_U32 * 4;
        const uint32_t BhiB = sb + 2 * A_T_U32 * 4;
        const uint32_t BloB = BhiB + B_T_U32 * 4;

#pragma unroll
        for (int ks = 0; ks < 2; ks++) {
            const int kofs = ks * 32;
            uint32_t bh[4][2], bl[4][2];
#pragma unroll
            for (int p = 0; p < 2; p++) {
                ldmx4(bh[2*p][0], bh[2*p][1], bh[2*p+1][0], bh[2*p+1][1],
                      BhiB + bRowOff[p] + kofs);
                ldmx4(bl[2*p][0], bl[2*p][1], bl[2*p+1][0], bl[2*p+1][1],
                      BloB + bRowOff[p] + kofs);
            }
#pragma unroll
            for (int mt = 0; mt < MTN; mt++) {
                uint32_t ah0, ah1, ah2, ah3, al0, al1, al2, al3;
                ldmx4(ah0, ah1, ah2, ah3, AhiB + aRowOff[mt] + kofs);
                ldmx4(al0, al1, al2, al3, AloB + aRowOff[mt] + kofs);
#pragma unroll
                for (int nt = 0; nt < 4; nt++) {
                    mma_bf16(c[mt][nt], al0, al1, al2, al3, bh[nt][0], bh[nt][1]);
                    mma_bf16(c[mt][nt], ah0, ah1, ah2, ah3, bl[nt][0], bl[nt][1]);
                    mma_bf16(c[mt][nt], ah0, ah1, ah2, ah3, bh[nt][0], bh[nt][1]);
                }
            }
        }
        __syncthreads();
    }

    // epilogue: c0,c1 -> (row g, cols 2tg,2tg+1), c2,c3 -> (row g+8)
    const int g  = lane >> 2;
    const int tg = lane & 3;
#pragma unroll
    for (int mt = 0; mt < MTN; mt++) {
        int row0 = by * ROWSA + mb + mt * 16 + g;
        int row1 = row0 + 8;
        float* c0p = C + (size_t)row0 * Ncols + bx * 128 + nb;
        float* c1p = C + (size_t)row1 * Ncols + bx * 128 + nb;
#pragma unroll
        for (int nt = 0; nt < 4; nt++) {
            int col = nt * 8 + tg * 2;
            *(float2*)(c0p + col) = make_float2(c[mt][nt][0], c[mt][nt][1]);
            *(float2*)(c1p + col) = make_float2(c[mt][nt][2], c[mt][nt][3]);
        }
    }
}

// ---------------- init h, m (f32 + packed), 64 threads float4 ----------------
__global__ void init_hm(const int* __restrict__ user_idxs,
                        const float* __restrict__ user_table) {
    int n = blockIdx.x;
    int t = threadIdx.x;    // 0..63
    float4 hv = *(const float4*)(user_table + (size_t)user_idxs[n] * DD + 4 * t);
    *(float4*)(g_h + n * DD + 4 * t) = hv;
    uint32_t hi0, lo0, hi1, lo1;
    split2(make_float2(hv.x, hv.y), hi0, lo0);
    split2(make_float2(hv.z, hv.w), hi1, lo1);
    g_h_hi[n * 128 + 2 * t]     = hi0;
    g_h_lo[n * 128 + 2 * t]     = lo0;
    g_h_hi[n * 128 + 2 * t + 1] = hi1;
    g_h_lo[n * 128 + 2 * t + 1] = lo1;
    if (t == 0) g_m[n] = 1.0f;
}

// ---------------- fused GRU gates + y + state update (64 thr, float4) -------
__device__ __forceinline__ float sigmoidf_(float x) {
    return 1.0f / (1.0f + expf(-x));
}

__global__ __launch_bounds__(64)
void gru_step(const float* __restrict__ b_ih,
              const float* __restrict__ b_hh,
              const float* __restrict__ W_out,
              const float* __restrict__ b_out,
              float* __restrict__ out,
              int s) {
    const int n = blockIdx.x;
    const int t = threadIdx.x;   // 0..63, handles cols 4t..4t+3

    const float* Grow  = g_G + ((size_t)s * NN + n) * NC;
    const float* ghrow = g_gh + (size_t)n * TD;

    float mm = g_m[n];
    float4 hv = *(const float4*)(g_h + n * DD + 4 * t);

    float4 Gr = *(const float4*)(Grow + 4 * t);
    float4 Gz = *(const float4*)(Grow + DD + 4 * t);
    float4 Gn = *(const float4*)(Grow + 2 * DD + 4 * t);
    float4 Mr = *(const float4*)(Grow + TD + 4 * t);
    float4 Mz = *(const float4*)(Grow + TD + DD + 4 * t);
    float4 Mn = *(const float4*)(Grow + TD + 2 * DD + 4 * t);
    float4 Hr = *(const float4*)(ghrow + 4 * t);
    float4 Hz = *(const float4*)(ghrow + DD + 4 * t);
    float4 Hn = *(const float4*)(ghrow + 2 * DD + 4 * t);
    float4 Br = *(const float4*)(b_ih + 4 * t);
    float4 Bz = *(const float4*)(b_ih + DD + 4 * t);
    float4 Bn = *(const float4*)(b_ih + 2 * DD + 4 * t);
    float4 Cr = *(const float4*)(b_hh + 4 * t);
    float4 Cz = *(const float4*)(b_hh + DD + 4 * t);
    float4 Cn = *(const float4*)(b_hh + 2 * DD + 4 * t);
    float4 Wo = *(const float4*)(W_out + 4 * t);

    float hn[4], hvv[4] = {hv.x, hv.y, hv.z, hv.w};
    float gr[4] = {Gr.x,Gr.y,Gr.z,Gr.w}, gz[4] = {Gz.x,Gz.y,Gz.z,Gz.w}, gn[4] = {Gn.x,Gn.y,Gn.z,Gn.w};
    float mr[4] = {Mr.x,Mr.y,Mr.z,Mr.w}, mz[4] = {Mz.x,Mz.y,Mz.z,Mz.w}, mn[4] = {Mn.x,Mn.y,Mn.z,Mn.w};
    float hr[4] = {Hr.x,Hr.y,Hr.z,Hr.w}, hz[4] = {Hz.x,Hz.y,Hz.z,Hz.w}, hnn[4] = {Hn.x,Hn.y,Hn.z,Hn.w};
    float br[4] = {Br.x,Br.y,Br.z,Br.w}, bz[4] = {Bz.x,Bz.y,Bz.z,Bz.w}, bn[4] = {Bn.x,Bn.y,Bn.z,Bn.w};
    float cr[4] = {Cr.x,Cr.y,Cr.z,Cr.w}, cz[4] = {Cz.x,Cz.y,Cz.z,Cz.w}, cn[4] = {Cn.x,Cn.y,Cn.z,Cn.w};
    float wo[4] = {Wo.x,Wo.y,Wo.z,Wo.w};

    float part = 0.0f;
#pragma unroll
    for (int e = 0; e < 4; e++) {
        float gir = gr[e] + mm * mr[e] + br[e];
        float giz = gz[e] + mm * mz[e] + bz[e];
        float gin = gn[e] + mm * mn[e] + bn[e];
        float ghr = hr[e] + cr[e];
        float ghz = hz[e] + cz[e];
        float ghn = hnn[e] + cn[e];
        float r  = sigmoidf_(gir + ghr);
        float z  = sigmoidf_(giz + ghz);
        float nv = tanhf(gin + r * ghn);
        hn[e] = (1.0f - z) * nv + z * hvv[e];
        part += hn[e] * wo[e];
    }

    *(float4*)(g_h + n * DD + 4 * t) = make_float4(hn[0], hn[1], hn[2], hn[3]);
    uint32_t hi0, lo0, hi1, lo1;
    split2(make_float2(hn[0], hn[1]), hi0, lo0);
    split2(make_float2(hn[2], hn[3]), hi1, lo1);
    g_h_hi[n * 128 + 2 * t]     = hi0;
    g_h_lo[n * 128 + 2 * t]     = lo0;
    g_h_hi[n * 128 + 2 * t + 1] = hi1;
    g_h_lo[n * 128 + 2 * t + 1] = lo1;

#pragma unroll
    for (int off = 16; off > 0; off >>= 1)
        part += __shfl_down_sync(0xFFFFFFFFu, part, off);

    __shared__ float warpsum[2];
    if ((t & 31) == 0) warpsum[t >> 5] = part;
    __syncthreads();
    if (t == 0) {
        float y = b_out[0] + warpsum[0] + warpsum[1];
        out[n * SS + s] = y;
        g_m[n] = sigmoidf_(y);
    }
}

// ---------------- launch ----------------
extern "C" void kernel_launch(void* const* d_in, const int* in_sizes, int n_in,
                              void* d_out, int out_size) {
    const int*   item_idxs  = (const int*)  d_in[0];
    const int*   user_idxs  = (const int*)  d_in[1];
    const float* item_table = (const float*)d_in[3];
    const float* user_table = (const float*)d_in[4];
    const float* W_ih       = (const float*)d_in[5];
    const float* W_hh       = (const float*)d_in[6];
    const float* b_ih       = (const float*)d_in[7];
    const float* b_hh       = (const float*)d_in[8];
    const float* W_out      = (const float*)d_in[9];
    const float* b_out      = (const float*)d_in[10];
    float* out = (float*)d_out;

    float *G_p, *gh_p;
    uint32_t *iTh, *iTl, *Wih_h, *Wih_l, *Whh_h, *Whh_l, *hh, *hl;
    cudaGetSymbolAddress((void**)&G_p,  g_G);
    cudaGetSymbolAddress((void**)&gh_p, g_gh);
    cudaGetSymbolAddress((void**)&iTh,  g_iT_hi);
    cudaGetSymbolAddress((void**)&iTl,  g_iT_lo);
    cudaGetSymbolAddress((void**)&Wih_h, g_Wih_hi);
    cudaGetSymbolAddress((void**)&Wih_l, g_Wih_lo);
    cudaGetSymbolAddress((void**)&Whh_h, g_Whh_hi);
    cudaGetSymbolAddress((void**)&Whh_l, g_Whh_lo);
    cudaGetSymbolAddress((void**)&hh,   g_h_hi);
    cudaGetSymbolAddress((void**)&hl,   g_h_lo);

    // smem sizes: MTN=4: 1024 + 2*40960 = 82944 ; MTN=2: 1024 + 2*30720 = 62464
    cudaFuncSetAttribute(gemm_tc<1,4>, cudaFuncAttributeMaxDynamicSharedMemorySize, 82944);
    cudaFuncSetAttribute(gemm_tc<0,2>, cudaFuncAttributeMaxDynamicSharedMemorySize, 62464);

    // one-time conversions
    conv_item<<<(NITEMS * 128 + 255) / 256, 256>>>(item_table);
    conv_wih<<<NC, 128>>>(W_ih);
    conv_whh<<<TD, 128>>>(W_hh);
    init_hm<<<NN, 64>>>(user_idxs, user_table);

    // precompute G = gather(E) @ [W1 | W2]^T   (M=81920, Ncols=1536, K=256)
    {
        dim3 grid(NC / 128, (SS * NN) / 128);   // 12 x 640
        gemm_tc<1,4><<<grid, 256, 82944>>>(iTh, iTl, Wih_h, Wih_l,
                                           G_p, NC, item_idxs);
    }

    // 20 sequential GRU steps
    for (int s = 0; s < SS; s++) {
        dim3 grid(TD / 128, NN / 64);           // 6 x 64
        gemm_tc<0,2><<<grid, 256, 62464>>>(hh, hl, Whh_h, Whh_l,
                                           gh_p, TD, nullptr);
        gru_step<<<NN, 64>>>(b_ih, b_hh, W_out, b_out, out, s);
    }
}